// round 13
// baseline (speedup 1.0000x reference)
#include <cuda_runtime.h>

// out[b,h,w] = sum_c x[b,h,w,c] * mask[h%8,w%8,c],
// mask = sigmoid(12*(sigmoid(5*w) - thresh)), x: (32,512,512,4) fp32 NHWC.
//
// R11 showed the limiter is now instruction overhead: every warp redundantly
// recomputed the SAME 64 mask values (~1M MUFU warp-instrs, issue=51%).
// R12: two-launch graph. Prologue <<<1,64>>> computes the 64-entry mask table
// once into a __device__ global; the streaming kernel (R10's best granularity:
// 16384 x 128-thread blocks, dense 512B warp loads) has NO transcendentals,
// NO smem, NO barriers: 1 warm mask LDG.128 + 4 x LDG.128 + 16 FFMA + 4 STG.

#define PMASK_SLOPE 5.0f
#define SAMPLE_SLOPE 12.0f

#define NPIX    (32 * 512 * 512)    // 8,388,608 pixels
#define NBLOCKS (NPIX / 512)        // 16384 blocks, 512 px each

__device__ float4 g_mask[64];       // [h8*8 + w8] -> per-channel mask

__device__ __forceinline__ float sigmoidf(float z) {
    return 1.0f / (1.0f + __expf(-z));
}

__global__ void mask_table_kernel(const float4* __restrict__ wv,
                                  const float4* __restrict__ tv)
{
    int i = threadIdx.x;   // 0..63
    float4 w4 = wv[i];
    float4 t4 = tv[i];
    float4 m;
    m.x = sigmoidf(SAMPLE_SLOPE * (sigmoidf(PMASK_SLOPE * w4.x) - t4.x));
    m.y = sigmoidf(SAMPLE_SLOPE * (sigmoidf(PMASK_SLOPE * w4.y) - t4.y));
    m.z = sigmoidf(SAMPLE_SLOPE * (sigmoidf(PMASK_SLOPE * w4.z) - t4.z));
    m.w = sigmoidf(SAMPLE_SLOPE * (sigmoidf(PMASK_SLOPE * w4.w) - t4.w));
    g_mask[i] = m;
}

__device__ __forceinline__ float dot4(float4 v, float4 m) {
    return v.x * m.x + v.y * m.y + v.z * m.z + v.w * m.w;
}

__global__ void __launch_bounds__(128)
probmask_kernel(const float4* __restrict__ x,
                float* __restrict__ out)
{
    int tid  = threadIdx.x;
    int lane = tid & 31;
    int warp = tid >> 5;                        // 0..3

    int row0  = blockIdx.x << 9;                // block's first pixel (one row)
    int base0 = row0 + (warp << 7);             // warp's 128-pixel dense tile
    int p     = base0 + lane;

    // 4 dense 512B warp loads (each LDG.128 touches exactly 4 cache lines).
    float4 v0 = x[p +  0];
    float4 v1 = x[p + 32];
    float4 v2 = x[p + 64];
    float4 v3 = x[p + 96];

    // One mask float4 per thread from the precomputed 1KB table (L2/L1 warm).
    // h%8 uniform over the row; w%8 of this lane's pixels (stride 32) = lane&7.
    int h8 = (row0 >> 9) & 7;
    float4 m = g_mask[(h8 << 3) + (lane & 7)];

    out[p +  0] = dot4(v0, m);
    out[p + 32] = dot4(v1, m);
    out[p + 64] = dot4(v2, m);
    out[p + 96] = dot4(v3, m);
}

extern "C" void kernel_launch(void* const* d_in, const int* in_sizes, int n_in,
                              void* d_out, int out_size)
{
    const float4* x  = (const float4*)d_in[0];
    const float4* wv = (const float4*)d_in[1];
    const float4* tv = (const float4*)d_in[2];
    float* out = (float*)d_out;

    mask_table_kernel<<<1, 64>>>(wv, tv);
    probmask_kernel<<<NBLOCKS, 128>>>(x, out);
}

// round 16
// speedup vs baseline: 1.0377x; 1.0377x over previous
#include <cuda_runtime.h>

// out[b,h,w] = sum_c x[b,h,w,c] * mask[h%8,w%8,c],
// mask = sigmoid(12*(sigmoid(5*w) - thresh)), x: (32,512,512,4) fp32 NHWC.
//
// FINAL (R10 config, re-confirmed): 16384 x 128-thread blocks, one image row
// per block. Controlled experiments R10/R11/R12 all measure 25.6us kernel time
// at ~5.9 TB/s across issue 12-51% / occ 60-80% -> this is the DRAM floor for
// a 4:1 read:write single-touch stream; single launch minimizes graph overhead.
//  - dense 512B warp loads: lane l handles pixels {l, l+32, l+64, l+96},
//    every LDG.128 touches exactly 4 cache lines
//  - 64-entry mask table built once per block in smem (8 MUFU x 64 threads),
//    one register float4 per thread afterward
//  - 4 x LDG.128 + 16 FFMA + 4 x STG.32 (dense) per thread, regs=28

#define PMASK_SLOPE 5.0f
#define SAMPLE_SLOPE 12.0f

#define NPIX    (32 * 512 * 512)    // 8,388,608 pixels
#define NBLOCKS (NPIX / 512)        // 16384 blocks, one row each

__device__ __forceinline__ float sigmoidf(float z) {
    return 1.0f / (1.0f + __expf(-z));
}

__device__ __forceinline__ float dot4(float4 v, float4 m) {
    return v.x * m.x + v.y * m.y + v.z * m.z + v.w * m.w;
}

__global__ void __launch_bounds__(128)
probmask_kernel(const float4* __restrict__ x,
                const float4* __restrict__ wv,
                const float4* __restrict__ tv,
                float* __restrict__ out)
{
    __shared__ float4 smask[64];   // [h8*8 + w8] -> per-channel mask

    int tid = threadIdx.x;
    if (tid < 64) {
        float4 w4 = wv[tid];
        float4 t4 = tv[tid];
        float4 m;
        m.x = sigmoidf(SAMPLE_SLOPE * (sigmoidf(PMASK_SLOPE * w4.x) - t4.x));
        m.y = sigmoidf(SAMPLE_SLOPE * (sigmoidf(PMASK_SLOPE * w4.y) - t4.y));
        m.z = sigmoidf(SAMPLE_SLOPE * (sigmoidf(PMASK_SLOPE * w4.z) - t4.z));
        m.w = sigmoidf(SAMPLE_SLOPE * (sigmoidf(PMASK_SLOPE * w4.w) - t4.w));
        smask[tid] = m;
    }
    __syncthreads();

    int lane = tid & 31;
    int warp = tid >> 5;                       // 0..3
    int row0 = blockIdx.x << 9;                // block's first pixel (one row)
    int base0 = row0 + (warp << 7);            // warp's 128-pixel tile

    // h%8 is uniform for the whole block (one image row); w%8 = lane&7
    // for this lane's pixels (stride 32 within the warp tile).
    int h8 = (row0 >> 9) & 7;
    float4 m = smask[(h8 << 3) + (lane & 7)];

    int p = base0 + lane;

    // 4 dense 512B warp loads; every LDG.128 touches exactly 4 cache lines.
    float4 v0 = x[p +  0];
    float4 v1 = x[p + 32];
    float4 v2 = x[p + 64];
    float4 v3 = x[p + 96];

    out[p +  0] = dot4(v0, m);
    out[p + 32] = dot4(v1, m);
    out[p + 64] = dot4(v2, m);
    out[p + 96] = dot4(v3, m);
}

extern "C" void kernel_launch(void* const* d_in, const int* in_sizes, int n_in,
                              void* d_out, int out_size)
{
    const float4* x  = (const float4*)d_in[0];
    const float4* wv = (const float4*)d_in[1];
    const float4* tv = (const float4*)d_in[2];
    float* out = (float*)d_out;

    probmask_kernel<<<NBLOCKS, 128>>>(x, wv, tv, out);
}

// round 17
// speedup vs baseline: 1.0760x; 1.0369x over previous
#include <cuda_runtime.h>

// out[b,h,w] = sum_c x[b,h,w,c] * mask[h%8,w%8,c],
// mask = sigmoid(12*(sigmoid(5*w) - thresh)), x: (32,512,512,4) fp32 NHWC.
//
// FINAL (R10 config, re-confirmed): 16384 x 128-thread blocks, one image row
// per block. Controlled experiments R10/R11/R12 all measure 25.6us kernel time
// at ~5.9 TB/s across issue 12-51% / occ 60-80% -> this is the DRAM floor for
// a 4:1 read:write single-touch stream; single launch minimizes graph overhead.
//  - dense 512B warp loads: lane l handles pixels {l, l+32, l+64, l+96},
//    every LDG.128 touches exactly 4 cache lines
//  - 64-entry mask table built once per block in smem (8 MUFU x 64 threads),
//    one register float4 per thread afterward
//  - 4 x LDG.128 + 16 FFMA + 4 x STG.32 (dense) per thread, regs=28

#define PMASK_SLOPE 5.0f
#define SAMPLE_SLOPE 12.0f

#define NPIX    (32 * 512 * 512)    // 8,388,608 pixels
#define NBLOCKS (NPIX / 512)        // 16384 blocks, one row each

__device__ __forceinline__ float sigmoidf(float z) {
    return 1.0f / (1.0f + __expf(-z));
}

__device__ __forceinline__ float dot4(float4 v, float4 m) {
    return v.x * m.x + v.y * m.y + v.z * m.z + v.w * m.w;
}

__global__ void __launch_bounds__(128)
probmask_kernel(const float4* __restrict__ x,
                const float4* __restrict__ wv,
                const float4* __restrict__ tv,
                float* __restrict__ out)
{
    __shared__ float4 smask[64];   // [h8*8 + w8] -> per-channel mask

    int tid = threadIdx.x;
    if (tid < 64) {
        float4 w4 = wv[tid];
        float4 t4 = tv[tid];
        float4 m;
        m.x = sigmoidf(SAMPLE_SLOPE * (sigmoidf(PMASK_SLOPE * w4.x) - t4.x));
        m.y = sigmoidf(SAMPLE_SLOPE * (sigmoidf(PMASK_SLOPE * w4.y) - t4.y));
        m.z = sigmoidf(SAMPLE_SLOPE * (sigmoidf(PMASK_SLOPE * w4.z) - t4.z));
        m.w = sigmoidf(SAMPLE_SLOPE * (sigmoidf(PMASK_SLOPE * w4.w) - t4.w));
        smask[tid] = m;
    }
    __syncthreads();

    int lane = tid & 31;
    int warp = tid >> 5;                       // 0..3
    int row0 = blockIdx.x << 9;                // block's first pixel (one row)
    int base0 = row0 + (warp << 7);            // warp's 128-pixel tile

    // h%8 is uniform for the whole block (one image row); w%8 = lane&7
    // for this lane's pixels (stride 32 within the warp tile).
    int h8 = (row0 >> 9) & 7;
    float4 m = smask[(h8 << 3) + (lane & 7)];

    int p = base0 + lane;

    // 4 dense 512B warp loads; every LDG.128 touches exactly 4 cache lines.
    float4 v0 = x[p +  0];
    float4 v1 = x[p + 32];
    float4 v2 = x[p + 64];
    float4 v3 = x[p + 96];

    out[p +  0] = dot4(v0, m);
    out[p + 32] = dot4(v1, m);
    out[p + 64] = dot4(v2, m);
    out[p + 96] = dot4(v3, m);
}

extern "C" void kernel_launch(void* const* d_in, const int* in_sizes, int n_in,
                              void* d_out, int out_size)
{
    const float4* x  = (const float4*)d_in[0];
    const float4* wv = (const float4*)d_in[1];
    const float4* tv = (const float4*)d_in[2];
    float* out = (float*)d_out;

    probmask_kernel<<<NBLOCKS, 128>>>(x, wv, tv, out);
}